// round 16
// baseline (speedup 1.0000x reference)
#include <cuda_runtime.h>
#include <cuda_fp16.h>
#include <math.h>
#include <stdint.h>

#define NB     128
#define NCELLS 81
#define NNODE  (NB*NCELLS)     // 10368
#define HD     96
#define TSTEPS 16
#define NTILES (NNODE/6)       // 1728 tiles of 6 nodes (120 edges + 8 pad)
#define CORR   (1.0f/2048.0f)
#define EGRID  152

// ========================= fp16 mma/ldmatrix helpers (sm_80+) =========================
#define MMAF(c,a0,a1,a2,a3,b0,b1) \
    asm volatile("mma.sync.aligned.m16n8k16.row.col.f32.f16.f16.f32 " \
        "{%0,%1,%2,%3}, {%4,%5,%6,%7}, {%8,%9}, {%0,%1,%2,%3};" \
        : "+f"((c)[0]),"+f"((c)[1]),"+f"((c)[2]),"+f"((c)[3]) \
        : "r"(a0),"r"(a1),"r"(a2),"r"(a3), "r"(b0),"r"(b1))
#define LDSM4(r0,r1,r2,r3,addr) \
    asm volatile("ldmatrix.sync.aligned.m8n8.x4.shared.b16 {%0,%1,%2,%3}, [%4];" \
        : "=r"(r0),"=r"(r1),"=r"(r2),"=r"(r3) : "r"(addr))
#define LDSM4T(r0,r1,r2,r3,addr) \
    asm volatile("ldmatrix.sync.aligned.m8n8.x4.trans.shared.b16 {%0,%1,%2,%3}, [%4];" \
        : "=r"(r0),"=r"(r1),"=r"(r2),"=r"(r3) : "r"(addr))

#define BAR_ARRIVE(id)  asm volatile("bar.arrive %0, 512;" :: "r"(id) : "memory")
#define BAR_SYNC512(id) asm volatile("bar.sync %0, 512;"   :: "r"(id) : "memory")

__device__ __forceinline__ uint32_t smem_u32(const void* p) {
    uint32_t a;
    asm("{ .reg .u64 t; cvta.to.shared.u64 t, %1; cvt.u32.u64 %0, t; }" : "=r"(a) : "l"(p));
    return a;
}
__device__ __forceinline__ uint32_t pk2(float a, float b) {
    __half2 h = __floats2half2_rn(a, b);
    return *(uint32_t*)&h;
}

// ========================= device scratch =========================
__device__ float  g_x[NNODE*HD];
__device__ float  g_gx[NNODE*4*HD];
__device__ float  g_S1[NNODE*6*HD];      // [a_src(96) | a_dst(96) | unused]
__device__ float  g_gm[NNODE*4*HD];      // gates contribution: [h|Z] @ [Whh;Wcomb]^T
__device__ float  g_c[NNODE*HD];
__device__ float  g_WTin[3*HD*HD];
__device__ float  g_WTin0[48*HD];
__device__ float  g_bc[384];
__device__ __half g_hH[NNODE*104], g_hL[NNODE*104];     // h hi/lo images (stride 104)
__device__ __half g_ZH[NNODE*104], g_ZL[NNODE*104];     // Z hi/lo images
__device__ __half g_Wmsg[4*96*104];                     // [W1h|W1l|W2h|W2l] k-major s104
__device__ __half g_WpackTH[96*576], g_WpackTL[96*576]; // k-major images of Wpack
__device__ __half g_WgateH[192*384], g_WgateL[192*384]; // [Whh(k<96); Wcomb(k>=96)] k-major
__device__ float  g_logits[(size_t)TSTEPS*NNODE*10];
__device__ double g_loss;

// ========================= weight packing =========================
__global__ void pack_kernel(const float* __restrict__ msg_W,
                            const float* __restrict__ in_W,
                            const float* __restrict__ in_W0,
                            const float* __restrict__ msg_W0,
                            const float* __restrict__ W_hh,
                            const float* __restrict__ W_ih,
                            const float* __restrict__ msg_b)
{
    int i = blockIdx.x*blockDim.x + threadIdx.x;
    int stride = gridDim.x*blockDim.x;
    for (int idx = i; idx < 3*HD*HD; idx += stride) {
        int l = idx / (HD*HD), r = idx % (HD*HD);
        int k = r / HD, j = r % HD;
        g_WTin[idx] = in_W[l*HD*HD + j*HD + k];
    }
    for (int idx = i; idx < 48*HD; idx += stride) {
        int k = idx / HD, j = idx % HD;
        g_WTin0[idx] = in_W0[j*48 + k];
    }
    for (int idx = i; idx < 4*96*104; idx += stride) {
        int part = idx / (96*104);
        int r2 = idx % (96*104);
        int k = r2 / 104, j = r2 % 104;
        int layer = part >> 1, which = part & 1;
        float w = (j < 96) ? msg_W[layer*HD*HD + j*HD + k] : 0.f;
        __half hh = __float2half_rn(w);
        g_Wmsg[idx] = which ? __float2half_rn((w - __half2float(hh))*2048.f) : hh;
    }
    for (int idx = i; idx < 96*576; idx += stride) {
        int k = idx / 576, o = idx % 576;
        float v;
        if (o < 96)       v = msg_W0[o*192 + k];
        else if (o < 192) v = msg_W0[(o-96)*192 + 96 + k];
        else              v = W_hh[(o-192)*HD + k];
        __half hh = __float2half_rn(v);
        g_WpackTH[idx] = hh;
        g_WpackTL[idx] = __float2half_rn((v - __half2float(hh))*2048.f);
    }
    // Wgate: k<96 -> W_hh[o][k]; k>=96 -> Wcomb[o][k-96] = sum_c W_ihm[o][c]*W3[c][k-96]
    for (int idx = i; idx < 192*384; idx += stride) {
        int k = idx / 384, o = idx % 384;
        float v;
        if (k < 96) {
            v = W_hh[o*96 + k];
        } else {
            int kk = k - 96;
            float s = 0.f;
            const float* wm = W_ih + o*192 + 96;
            const float* w3 = msg_W + 2*HD*HD + kk;
            #pragma unroll 8
            for (int c = 0; c < 96; c++) s = fmaf(wm[c], w3[c*96], s);
            v = s;
        }
        __half hh = __float2half_rn(v);
        g_WgateH[idx] = hh;
        g_WgateL[idx] = __float2half_rn((v - __half2float(hh))*2048.f);
    }
    for (int idx = i; idx < 384; idx += stride) {
        float s = 0.f;
        #pragma unroll 8
        for (int c = 0; c < 96; c++) s = fmaf(W_ih[idx*192+96+c], msg_b[288+c], s);
        g_bc[idx] = 20.f * s;
    }
    if (i == 0) g_loss = 0.0;
}

// ========================= fp32 sgemm (gx, once) =========================
__global__ void __launch_bounds__(256) sgemm_awt(const float* __restrict__ A,
                                                 const float* __restrict__ W,
                                                 float* __restrict__ C,
                                                 int Nc, int ldw, int woff)
{
    __shared__ float As[16][68];
    __shared__ float Ws[16][68];
    int bm = blockIdx.y * 64, bn = blockIdx.x * 64;
    int tid = threadIdx.x;
    int tx = tid & 15, ty = tid >> 4;
    int lr = tid >> 2, lk = (tid & 3) << 2;
    float acc[4][4];
    #pragma unroll
    for (int i = 0; i < 4; i++)
        #pragma unroll
        for (int j = 0; j < 4; j++) acc[i][j] = 0.f;

    for (int k0 = 0; k0 < 96; k0 += 16) {
        float4 a = *(const float4*)(A + (size_t)(bm+lr)*96 + k0 + lk);
        As[lk+0][lr]=a.x; As[lk+1][lr]=a.y; As[lk+2][lr]=a.z; As[lk+3][lr]=a.w;
        float4 w = *(const float4*)(W + (size_t)(bn+lr)*ldw + woff + k0 + lk);
        Ws[lk+0][lr]=w.x; Ws[lk+1][lr]=w.y; Ws[lk+2][lr]=w.z; Ws[lk+3][lr]=w.w;
        __syncthreads();
        #pragma unroll
        for (int k = 0; k < 16; k++) {
            float4 a4 = *(const float4*)&As[k][ty*4];
            float4 w4 = *(const float4*)&Ws[k][tx*4];
            float av[4] = {a4.x, a4.y, a4.z, a4.w};
            float wv[4] = {w4.x, w4.y, w4.z, w4.w};
            #pragma unroll
            for (int i = 0; i < 4; i++)
                #pragma unroll
                for (int j = 0; j < 4; j++)
                    acc[i][j] = fmaf(av[i], wv[j], acc[i][j]);
        }
        __syncthreads();
    }
    #pragma unroll
    for (int i = 0; i < 4; i++) {
        float4 o = make_float4(acc[i][0], acc[i][1], acc[i][2], acc[i][3]);
        *(float4*)(C + (size_t)(bm + ty*4 + i)*Nc + bn + tx*4) = o;
    }
}

// ========================= fp16 3-term GEMM: C = A @ W^T (S1, k=96) =========================
#define GEMM_SMEM (2*64*104*2 + 2*96*72*2)   // 54272

__global__ void __launch_bounds__(256) gemm_f16(const __half* __restrict__ AH,
                                                const __half* __restrict__ AL,
                                                const __half* __restrict__ BH,
                                                const __half* __restrict__ BL,
                                                float* __restrict__ C, int Nc)
{
    extern __shared__ char sg[];
    __half* sA = (__half*)sg;
    __half* sB = (__half*)(sg + 2*64*104*2);
    int bm = blockIdx.y*64, bn = blockIdx.x*64;
    int tid = threadIdx.x, lane = tid & 31, wid = tid >> 5;

    {
        const uint4* gh = (const uint4*)(AH + (size_t)bm*104);
        const uint4* gl = (const uint4*)(AL + (size_t)bm*104);
        uint4* dh = (uint4*)sA;
        uint4* dl = (uint4*)(sA + 64*104);
        for (int i = tid; i < 832; i += 256) { dh[i] = gh[i]; dl[i] = gl[i]; }
        for (int i = tid; i < 2*96*8; i += 256) {
            int part = i / 768, r2 = i % 768;
            int k = r2 >> 3, c8 = (r2 & 7) * 8;
            const __half* src = (part ? BL : BH) + (size_t)k*Nc + bn + c8;
            *(uint4*)(sB + part*96*72 + k*72 + c8) = *(const uint4*)src;
        }
    }
    __syncthreads();

    int mtile = wid >> 1, nhalf = wid & 1;
    uint32_t aHb = smem_u32(sA) + (uint32_t)(((mtile*16 + (lane&15))*104 + ((lane>>4)<<3))*2);
    uint32_t aLb = aHb + 64*104*2;
    uint32_t bHb = smem_u32(sB) + (uint32_t)((((lane&15))*72 + nhalf*32 + ((lane>>4)<<3))*2);
    uint32_t bLb = bHb + 96*72*2;

    float am[4][4], ac[4][4];
    #pragma unroll
    for (int nt = 0; nt < 4; nt++)
        #pragma unroll
        for (int j = 0; j < 4; j++) { am[nt][j] = 0.f; ac[nt][j] = 0.f; }

    #pragma unroll
    for (int kt = 0; kt < 6; kt++) {
        uint32_t A0,A1,A2,A3, L0,L1,L2,L3;
        LDSM4(A0,A1,A2,A3, aHb + kt*32);
        LDSM4(L0,L1,L2,L3, aLb + kt*32);
        uint32_t h0,h1,h2,h3, hh0,hh1,hh2,hh3;
        uint32_t l0,l1,l2,l3, ll0,ll1,ll2,ll3;
        LDSM4T(h0,h1,h2,h3,     bHb + kt*2304);
        LDSM4T(hh0,hh1,hh2,hh3, bHb + kt*2304 + 32);
        LDSM4T(l0,l1,l2,l3,     bLb + kt*2304);
        LDSM4T(ll0,ll1,ll2,ll3, bLb + kt*2304 + 32);
        MMAF(am[0], A0,A1,A2,A3, h0,h1);
        MMAF(am[1], A0,A1,A2,A3, h2,h3);
        MMAF(am[2], A0,A1,A2,A3, hh0,hh1);
        MMAF(am[3], A0,A1,A2,A3, hh2,hh3);
        MMAF(ac[0], L0,L1,L2,L3, h0,h1);
        MMAF(ac[1], L0,L1,L2,L3, h2,h3);
        MMAF(ac[2], L0,L1,L2,L3, hh0,hh1);
        MMAF(ac[3], L0,L1,L2,L3, hh2,hh3);
        MMAF(ac[0], A0,A1,A2,A3, l0,l1);
        MMAF(ac[1], A0,A1,A2,A3, l2,l3);
        MMAF(ac[2], A0,A1,A2,A3, ll0,ll1);
        MMAF(ac[3], A0,A1,A2,A3, ll2,ll3);
    }

    int r0 = mtile*16 + (lane >> 2);
    int cb = (lane & 3) * 2;
    #pragma unroll
    for (int nt = 0; nt < 4; nt++) {
        int c = bn + nhalf*32 + nt*8 + cb;
        *(float2*)(C + (size_t)(bm+r0)*Nc + c) =
            make_float2(am[nt][0] + ac[nt][0]*CORR, am[nt][1] + ac[nt][1]*CORR);
        *(float2*)(C + (size_t)(bm+r0+8)*Nc + c) =
            make_float2(am[nt][2] + ac[nt][2]*CORR, am[nt][3] + ac[nt][3]*CORR);
    }
}

// ========================= gates GEMM: gm = [h|Z] @ [Whh;Wcomb]^T (k=192) =========================
// A: 64 rows x 192 cols built from h images (0-95, zero at t=0) + Z images (96-191).
// smem: AH 64x216 | AL 64x216 | BH 192x72 | BL 192x72
#define GA_ST   216
#define GG_SMEM (2*64*GA_ST*2 + 2*192*72*2)   // 55296 + 55296 = 110592

__global__ void __launch_bounds__(256) gemm_gates(const __half* __restrict__ hH,
                                                  const __half* __restrict__ hL,
                                                  const __half* __restrict__ ZH,
                                                  const __half* __restrict__ ZL,
                                                  float* __restrict__ C, int t)
{
    extern __shared__ char sg[];
    __half* sA = (__half*)sg;                      // hi 64x216 then lo 64x216
    __half* sB = (__half*)(sg + 2*64*GA_ST*2);     // hi 192x72 then lo 192x72
    int bm = blockIdx.y*64, bn = blockIdx.x*64;
    int tid = threadIdx.x, lane = tid & 31, wid = tid >> 5;

    for (int i = tid; i < 64*24; i += 256) {
        int r = i / 24, u = i % 24;
        uint4 vh, vl;
        if (u < 12) {
            if (t == 0) { vh = make_uint4(0,0,0,0); vl = vh; }
            else {
                vh = *(const uint4*)(hH + (size_t)(bm+r)*104 + u*8);
                vl = *(const uint4*)(hL + (size_t)(bm+r)*104 + u*8);
            }
        } else {
            vh = *(const uint4*)(ZH + (size_t)(bm+r)*104 + (u-12)*8);
            vl = *(const uint4*)(ZL + (size_t)(bm+r)*104 + (u-12)*8);
        }
        *(uint4*)(sA + r*GA_ST + u*8)             = vh;
        *(uint4*)(sA + 64*GA_ST + r*GA_ST + u*8)  = vl;
    }
    for (int i = tid; i < 2*192*8; i += 256) {
        int part = i / (192*8), r2 = i % (192*8);
        int k = r2 >> 3, c8 = (r2 & 7) * 8;
        const __half* src = (part ? g_WgateL : g_WgateH) + (size_t)k*384 + bn + c8;
        *(uint4*)(sB + part*192*72 + k*72 + c8) = *(const uint4*)src;
    }
    __syncthreads();

    int mtile = wid >> 1, nhalf = wid & 1;
    uint32_t aHb = smem_u32(sA) + (uint32_t)(((mtile*16 + (lane&15))*GA_ST + ((lane>>4)<<3))*2);
    uint32_t aLb = aHb + 64*GA_ST*2;
    uint32_t bHb = smem_u32(sB) + (uint32_t)((((lane&15))*72 + nhalf*32 + ((lane>>4)<<3))*2);
    uint32_t bLb = bHb + 192*72*2;

    float am[4][4], ac[4][4];
    #pragma unroll
    for (int nt = 0; nt < 4; nt++)
        #pragma unroll
        for (int j = 0; j < 4; j++) { am[nt][j] = 0.f; ac[nt][j] = 0.f; }

    #pragma unroll
    for (int kt = 0; kt < 12; kt++) {
        uint32_t A0,A1,A2,A3, L0,L1,L2,L3;
        LDSM4(A0,A1,A2,A3, aHb + kt*32);
        LDSM4(L0,L1,L2,L3, aLb + kt*32);
        uint32_t h0,h1,h2,h3, hh0,hh1,hh2,hh3;
        uint32_t l0,l1,l2,l3, ll0,ll1,ll2,ll3;
        LDSM4T(h0,h1,h2,h3,     bHb + kt*2304);
        LDSM4T(hh0,hh1,hh2,hh3, bHb + kt*2304 + 32);
        LDSM4T(l0,l1,l2,l3,     bLb + kt*2304);
        LDSM4T(ll0,ll1,ll2,ll3, bLb + kt*2304 + 32);
        MMAF(am[0], A0,A1,A2,A3, h0,h1);
        MMAF(am[1], A0,A1,A2,A3, h2,h3);
        MMAF(am[2], A0,A1,A2,A3, hh0,hh1);
        MMAF(am[3], A0,A1,A2,A3, hh2,hh3);
        MMAF(ac[0], L0,L1,L2,L3, h0,h1);
        MMAF(ac[1], L0,L1,L2,L3, h2,h3);
        MMAF(ac[2], L0,L1,L2,L3, hh0,hh1);
        MMAF(ac[3], L0,L1,L2,L3, hh2,hh3);
        MMAF(ac[0], A0,A1,A2,A3, l0,l1);
        MMAF(ac[1], A0,A1,A2,A3, l2,l3);
        MMAF(ac[2], A0,A1,A2,A3, ll0,ll1);
        MMAF(ac[3], A0,A1,A2,A3, ll2,ll3);
    }

    int r0 = mtile*16 + (lane >> 2);
    int cb = (lane & 3) * 2;
    #pragma unroll
    for (int nt = 0; nt < 4; nt++) {
        int c = bn + nhalf*32 + nt*8 + cb;
        *(float2*)(C + (size_t)(bm+r0)*384 + c) =
            make_float2(am[nt][0] + ac[nt][0]*CORR, am[nt][1] + ac[nt][1]*CORR);
        *(float2*)(C + (size_t)(bm+r0+8)*384 + c) =
            make_float2(am[nt][2] + ac[nt][2]*CORR, am[nt][3] + ac[nt][3]*CORR);
    }
}

// ========================= input embedding + MLP =========================
__device__ __forceinline__ float dot96(const float* __restrict__ WTcol,
                                       const float* __restrict__ vin)
{
    float s = 0.f;
    #pragma unroll 8
    for (int k4 = 0; k4 < 24; k4++) {
        float4 a = ((const float4*)vin)[k4];
        s = fmaf(WTcol[(4*k4+0)*96], a.x, s);
        s = fmaf(WTcol[(4*k4+1)*96], a.y, s);
        s = fmaf(WTcol[(4*k4+2)*96], a.z, s);
        s = fmaf(WTcol[(4*k4+3)*96], a.w, s);
    }
    return s;
}

__global__ void __launch_bounds__(768) input_kernel(const int* __restrict__ q,
    const int* __restrict__ rw, const int* __restrict__ cl,
    const float* __restrict__ demb, const float* __restrict__ remb,
    const float* __restrict__ cemb, const float* __restrict__ inb)
{
    extern __shared__ float sm[];
    float* sW0 = sm;
    float* sWT = sm + 48*96;
    float* svb = sWT + 3*9216;
    for (int i = threadIdx.x; i < 48*96;  i += 768) sW0[i] = g_WTin0[i];
    for (int i = threadIdx.x; i < 3*9216; i += 768) sWT[i] = g_WTin[i];
    __syncthreads();

    int slot = threadIdx.x / 96, j = threadIdx.x % 96;
    float* v0 = svb + slot*240;
    float* vA = v0 + 48;
    float* vB = vA + 96;
    int sg = blockIdx.x*8 + slot;
    int stride = gridDim.x*8;
    int iters = (NNODE + stride - 1) / stride;
    float b0 = inb[j], b1 = inb[96+j], b2 = inb[192+j], b3 = inb[288+j];

    for (int it = 0; it < iters; it++) {
        int node = sg + it*stride;
        bool act = node < NNODE;
        int n = act ? node : NNODE-1;
        if (j < 16)      v0[j] = demb[q[n]*16 + j];
        else if (j < 32) v0[j] = remb[rw[n]*16 + (j-16)];
        else if (j < 48) v0[j] = cemb[cl[n]*16 + (j-32)];
        __syncthreads();
        float s = b0;
        #pragma unroll
        for (int k4 = 0; k4 < 12; k4++) {
            float4 a = ((const float4*)v0)[k4];
            s = fmaf(sW0[(4*k4+0)*96+j], a.x, s);
            s = fmaf(sW0[(4*k4+1)*96+j], a.y, s);
            s = fmaf(sW0[(4*k4+2)*96+j], a.z, s);
            s = fmaf(sW0[(4*k4+3)*96+j], a.w, s);
        }
        vA[j] = fmaxf(s, 0.f);
        __syncthreads();
        float t1 = b1 + dot96(sWT + j, vA);
        vB[j] = fmaxf(t1, 0.f);
        __syncthreads();
        float t2 = b2 + dot96(sWT + 9216 + j, vB);
        vA[j] = fmaxf(t2, 0.f);
        __syncthreads();
        float t3 = b3 + dot96(sWT + 2*9216 + j, vA);
        if (act) {
            g_x[(size_t)node*96 + j] = t3;
            __half hh = __float2half_rn(t3);
            g_hH[(size_t)node*104 + j] = hh;
            g_hL[(size_t)node*104 + j] = __float2half_rn((t3 - __half2float(hh))*2048.f);
            g_c[(size_t)node*96 + j] = 0.f;
        }
        __syncthreads();
    }
}

// ========================= warp-specialized fp16 HMMA edge pipeline (R11) =========================
#define OFF_B0     0
#define OFF_B1     384
#define OFF_B2     768
#define OFF_NBR    1152
#define OFF_W      7680
#define OFF_A      87552
#define ARS        432
#define SLOT       (128*ARS)
#define EK_SMEM    (OFF_A + 2*SLOT)  // 198144
#define WIMG       19968

__device__ __forceinline__ void edge_layer12(uint32_t aH, uint32_t aL,
                                             uint32_t wH, uint32_t wL,
                                             float (*am)[4], float (*ac)[4])
{
    #pragma unroll
    for (int kt = 0; kt < 6; kt++) {
        uint32_t A0,A1,A2,A3, L0,L1,L2,L3;
        LDSM4(A0,A1,A2,A3, aH + kt*32);
        LDSM4(L0,L1,L2,L3, aL + kt*32);
        #pragma unroll
        for (int np = 0; np < 3; np++) {
            uint32_t h0,h1,h2,h3, hh0,hh1,hh2,hh3;
            uint32_t l0,l1,l2,l3, ll0,ll1,ll2,ll3;
            uint32_t base = kt*3328 + np*64;
            LDSM4T(h0,h1,h2,h3,     wH + base);
            LDSM4T(hh0,hh1,hh2,hh3, wH + base + 32);
            LDSM4T(l0,l1,l2,l3,     wL + base);
            LDSM4T(ll0,ll1,ll2,ll3, wL + base + 32);
            int n0 = np*4;
            MMAF(am[n0  ], A0,A1,A2,A3, h0,h1);
            MMAF(am[n0+1], A0,A1,A2,A3, h2,h3);
            MMAF(am[n0+2], A0,A1,A2,A3, hh0,hh1);
            MMAF(am[n0+3], A0,A1,A2,A3, hh2,hh3);
            MMAF(ac[n0  ], L0,L1,L2,L3, h0,h1);
            MMAF(ac[n0+1], L0,L1,L2,L3, h2,h3);
            MMAF(ac[n0+2], L0,L1,L2,L3, hh0,hh1);
            MMAF(ac[n0+3], L0,L1,L2,L3, hh2,hh3);
            MMAF(ac[n0  ], A0,A1,A2,A3, l0,l1);
            MMAF(ac[n0+1], A0,A1,A2,A3, l2,l3);
            MMAF(ac[n0+2], A0,A1,A2,A3, ll0,ll1);
            MMAF(ac[n0+3], A0,A1,A2,A3, ll2,ll3);
        }
    }
}

__device__ __forceinline__ void build_tile(char* slotc, int g, int rB, int half,
                                           const int* __restrict__ snbr,
                                           const float* __restrict__ sb0)
{
    char* rowb = slotc + rB*ARS;
    if (rB < 120) {
        int dnode = g*6 + rB/20;
        int cell = dnode % 81;
        int srcn = dnode - cell + snbr[cell*20 + (rB % 20)];
        const float4* aS = (const float4*)(g_S1 + (size_t)srcn*576 + half*48);
        const float4* aD = (const float4*)(g_S1 + (size_t)dnode*576 + 96 + half*48);
        const float4* bB = (const float4*)(sb0 + half*48);
        #pragma unroll 4
        for (int k4 = 0; k4 < 12; k4++) {
            float4 s = aS[k4], d = aD[k4], b = bB[k4];
            float v0 = fmaxf(s.x+d.x+b.x, 0.f);
            float v1 = fmaxf(s.y+d.y+b.y, 0.f);
            float v2 = fmaxf(s.z+d.z+b.z, 0.f);
            float v3 = fmaxf(s.w+d.w+b.w, 0.f);
            int c = half*48 + k4*4;
            uint32_t h01 = pk2(v0, v1), h23 = pk2(v2, v3);
            float2 f01 = __half22float2(*(__half2*)&h01);
            float2 f23 = __half22float2(*(__half2*)&h23);
            *(uint32_t*)(rowb + c*2)           = h01;
            *(uint32_t*)(rowb + c*2 + 4)       = h23;
            *(uint32_t*)(rowb + 208 + c*2)     = pk2((v0-f01.x)*2048.f, (v1-f01.y)*2048.f);
            *(uint32_t*)(rowb + 208 + c*2 + 4) = pk2((v2-f23.x)*2048.f, (v3-f23.y)*2048.f);
        }
    } else {
        #pragma unroll 4
        for (int k4 = 0; k4 < 12; k4++) {
            int c = half*48 + k4*4;
            *(uint32_t*)(rowb + c*2)           = 0u;
            *(uint32_t*)(rowb + c*2 + 4)       = 0u;
            *(uint32_t*)(rowb + 208 + c*2)     = 0u;
            *(uint32_t*)(rowb + 208 + c*2 + 4) = 0u;
        }
    }
}

__global__ void __launch_bounds__(512, 1) edge_tc_kernel(const float* __restrict__ msgb)
{
    extern __shared__ char smc[];
    uint32_t sbase = smem_u32(smc);
    float* sb0 = (float*)(smc + OFF_B0);
    float* sb1 = (float*)(smc + OFF_B1);
    float* sb2 = (float*)(smc + OFF_B2);
    int*  snbr = (int*)(smc + OFF_NBR);
    int tid = threadIdx.x, lane = tid & 31, wid = tid >> 5;

    if (tid < 96) { sb0[tid]=msgb[tid]; sb1[tid]=msgb[96+tid]; sb2[tid]=msgb[192+tid]; }
    if (tid < 81) {
        int u = tid;
        int ru = u/9, cu = u%9, bu = (ru/3)*3 + cu/3;
        int cnt = 0;
        for (int v = 0; v < 81; v++) {
            if (v == u) continue;
            int rv = v/9, cv = v%9, bv = (rv/3)*3 + cv/3;
            if (rv == ru || cv == cu || bv == bu) snbr[u*20 + cnt++] = v;
        }
    }
    for (int i = tid; i < 4992; i += 512)
        ((uint4*)(smc + OFF_W))[i] = ((const uint4*)g_Wmsg)[i];
    __syncthreads();

    int bid = blockIdx.x;
    int n = (NTILES - bid + EGRID - 1) / EGRID;

    if (wid < 8) {
        int w = wid;
        uint32_t wfo = (uint32_t)((((lane&15))*104 + ((lane>>4)<<3))*2);
        uint32_t w1h = sbase + OFF_W + wfo;
        uint32_t w1l = w1h + WIMG;
        uint32_t w2h = w1h + 2*WIMG;
        uint32_t w2l = w1h + 3*WIMG;
        int cb = (lane & 3) * 2;
        int rfr = lane >> 2;
        int s = 0;

        for (int it = 0; it < n; it++) {
            BAR_SYNC512(1+s);
            char* slotc = smc + OFF_A + s*SLOT;
            uint32_t slotu = sbase + OFF_A + s*SLOT;
            uint32_t aH = slotu + (uint32_t)((w*16 + (lane&15))*ARS + ((lane>>4)<<4));
            uint32_t aL = aH + 208;

            float am[12][4], ac[12][4];
            #pragma unroll
            for (int nt = 0; nt < 12; nt++) {
                int c = nt*8 + cb;
                am[nt][0]=sb1[c]; am[nt][1]=sb1[c+1]; am[nt][2]=sb1[c]; am[nt][3]=sb1[c+1];
                ac[nt][0]=0.f; ac[nt][1]=0.f; ac[nt][2]=0.f; ac[nt][3]=0.f;
            }
            edge_layer12(aH, aL, w1h, w1l, am, ac);
            {
                int r0 = w*16 + rfr;
                char* rA0 = slotc + r0*ARS;
                char* rA8 = slotc + (r0+8)*ARS;
                #pragma unroll
                for (int nt = 0; nt < 12; nt++) {
                    int c = nt*8 + cb;
                    float v0 = fmaxf(am[nt][0] + ac[nt][0]*CORR, 0.f);
                    float v1 = fmaxf(am[nt][1] + ac[nt][1]*CORR, 0.f);
                    float v2 = fmaxf(am[nt][2] + ac[nt][2]*CORR, 0.f);
                    float v3 = fmaxf(am[nt][3] + ac[nt][3]*CORR, 0.f);
                    uint32_t h01 = pk2(v0, v1), h23 = pk2(v2, v3);
                    float2 f01 = __half22float2(*(__half2*)&h01);
                    float2 f23 = __half22float2(*(__half2*)&h23);
                    *(uint32_t*)(rA0 + c*2)       = h01;
                    *(uint32_t*)(rA8 + c*2)       = h23;
                    *(uint32_t*)(rA0 + 208 + c*2) = pk2((v0-f01.x)*2048.f, (v1-f01.y)*2048.f);
                    *(uint32_t*)(rA8 + 208 + c*2) = pk2((v2-f23.x)*2048.f, (v3-f23.y)*2048.f);
                }
            }
            __syncwarp();

            #pragma unroll
            for (int nt = 0; nt < 12; nt++) {
                int c = nt*8 + cb;
                am[nt][0]=sb2[c]; am[nt][1]=sb2[c+1]; am[nt][2]=sb2[c]; am[nt][3]=sb2[c+1];
                ac[nt][0]=0.f; ac[nt][1]=0.f; ac[nt][2]=0.f; ac[nt][3]=0.f;
            }
            edge_layer12(aH, aL, w2h, w2l, am, ac);
            {
                float* stg = (float*)slotc;
                int r0 = w*16 + rfr;
                #pragma unroll
                for (int nt = 0; nt < 12; nt++) {
                    int c = nt*8 + cb;
                    stg[r0*108 + c]       = fmaxf(am[nt][0] + ac[nt][0]*CORR, 0.f);
                    stg[r0*108 + c + 1]   = fmaxf(am[nt][1] + ac[nt][1]*CORR, 0.f);
                    stg[(r0+8)*108 + c]   = fmaxf(am[nt][2] + ac[nt][2]*CORR, 0.f);
                    stg[(r0+8)*108 + c+1] = fmaxf(am[nt][3] + ac[nt][3]*CORR, 0.f);
                }
            }
            BAR_ARRIVE(3+s);
            s ^= 1;
        }
    } else {
        int t = tid - 256;
        int rB = t & 127, half = t >> 7;

        build_tile(smc + OFF_A,        bid,         rB, half, snbr, sb0);
        BAR_ARRIVE(1);
        build_tile(smc + OFF_A + SLOT, bid + EGRID, rB, half, snbr, sb0);
        BAR_ARRIVE(2);

        int s = 0;
        for (int it = 0; it < n; it++) {
            BAR_SYNC512(3+s);
            float* stg = (float*)(smc + OFF_A + s*SLOT);
            int g = bid + it*EGRID;
            for (int idx = t; idx < 576; idx += 256) {
                int i = idx / 96, c = idx % 96;
                float sum = 0.f;
                #pragma unroll
                for (int e = 0; e < 20; e++) sum += stg[(i*20+e)*108 + c];
                __half hh = __float2half_rn(sum);
                size_t o = (size_t)(g*6+i)*104 + c;
                g_ZH[o] = hh;
                g_ZL[o] = __float2half_rn((sum - __half2float(hh))*2048.f);
            }
            int itn = it + 2;
            if (itn < n)
                build_tile(smc + OFF_A + s*SLOT, bid + itn*EGRID, rB, half, snbr, sb0);
            BAR_ARRIVE(1+s);
            s ^= 1;
        }
    }
}

// ========================= LSTM pointwise + per-step logits =========================
__global__ void __launch_bounds__(768) lstm_kernel(const float* __restrict__ outW,
                                                   const float* __restrict__ outb, int t)
{
    int slot = threadIdx.x / 96, j = threadIdx.x % 96;
    int n = blockIdx.x*8 + slot;
    __shared__ float sh[8][HD];
    size_t b4 = (size_t)n*384 + j;
    float gi = g_gx[b4      ] + g_gm[b4      ] + g_bc[j];
    float gf = g_gx[b4 +  96] + g_gm[b4 +  96] + g_bc[96+j];
    float gg = g_gx[b4 + 192] + g_gm[b4 + 192] + g_bc[192+j];
    float go = g_gx[b4 + 288] + g_gm[b4 + 288] + g_bc[288+j];
    float si = 1.f/(1.f + expf(-gi));
    float sf = 1.f/(1.f + expf(-gf));
    float so = 1.f/(1.f + expf(-go));
    float cn = sf * g_c[(size_t)n*96 + j] + si * tanhf(gg);
    float hn = so * tanhf(cn);
    g_c[(size_t)n*96 + j] = cn;
    __half hh = __float2half_rn(hn);
    g_hH[(size_t)n*104 + j] = hh;
    g_hL[(size_t)n*104 + j] = __float2half_rn((hn - __half2float(hh))*2048.f);
    sh[slot][j] = hn;
    __syncthreads();
    if (j < 10) {
        float s = outb[j];
        const float* w = outW + j*96;
        #pragma unroll 8
        for (int k = 0; k < 96; k++) s = fmaf(sh[slot][k], w[k], s);
        g_logits[((size_t)t*NNODE + n)*10 + j] = s;
    }
}

// ========================= preds / loss / lf =========================
__global__ void finalize_kernel(const int* __restrict__ labels,
                                float* __restrict__ out, int out_size)
{
    int idx = blockIdx.x*blockDim.x + threadIdx.x;
    double term = 0.0;
    if (idx < TSTEPS*NNODE) {
        const float* l = g_logits + (size_t)idx*10;
        float mx = l[0]; int am = 0;
        #pragma unroll
        for (int d = 1; d < 10; d++) if (l[d] > mx) { mx = l[d]; am = d; }
        float se = 0.f;
        #pragma unroll
        for (int d = 0; d < 10; d++) se += expf(l[d] - mx);
        float lse = mx + logf(se);
        int lab = labels[idx % NNODE];
        term = (double)(lse - l[lab]);

        const int FULL = TSTEPS*NNODE*11 + 1;
        if (out_size >= FULL) {
            out[idx] = (float)am;
            float* lf = out + TSTEPS*NNODE + 1 + (size_t)idx*10;
            #pragma unroll
            for (int d = 0; d < 10; d++) lf[d] = l[d];
        } else {
            float* lf = out + (size_t)idx*10;
            #pragma unroll
            for (int d = 0; d < 10; d++) lf[d] = l[d];
        }
    }
    #pragma unroll
    for (int o = 16; o; o >>= 1)
        term += __shfl_down_sync(0xffffffffu, term, o);
    if ((threadIdx.x & 31) == 0 && term != 0.0) atomicAdd(&g_loss, term);
}

__global__ void loss_kernel(float* __restrict__ out, int out_size)
{
    const int FULL = TSTEPS*NNODE*11 + 1;
    if (out_size >= FULL)
        out[TSTEPS*NNODE] = (float)(g_loss / (double)(TSTEPS*NNODE));
}

// ========================= launch =========================
extern "C" void kernel_launch(void* const* d_in, const int* in_sizes, int n_in,
                              void* d_out, int out_size)
{
    const int*   q      = (const int*)  d_in[0];
    const int*   row    = (const int*)  d_in[1];
    const int*   col    = (const int*)  d_in[2];
    const int*   labels = (const int*)  d_in[3];
    const float* d_emb  = (const float*)d_in[6];
    const float* r_emb  = (const float*)d_in[7];
    const float* c_emb  = (const float*)d_in[8];
    const float* in_W0  = (const float*)d_in[9];
    const float* in_W   = (const float*)d_in[10];
    const float* in_b   = (const float*)d_in[11];
    const float* msg_W0 = (const float*)d_in[12];
    const float* msg_W  = (const float*)d_in[13];
    const float* msg_b  = (const float*)d_in[14];
    const float* W_ih   = (const float*)d_in[15];
    const float* W_hh   = (const float*)d_in[16];
    const float* out_W  = (const float*)d_in[17];
    const float* out_b  = (const float*)d_in[18];
    float* out = (float*)d_out;

    const int IN_SMEM = (48*96 + 3*9216 + 8*240) * 4;
    cudaFuncSetAttribute(input_kernel,   cudaFuncAttributeMaxDynamicSharedMemorySize, IN_SMEM);
    cudaFuncSetAttribute(edge_tc_kernel, cudaFuncAttributeMaxDynamicSharedMemorySize, EK_SMEM);
    cudaFuncSetAttribute(gemm_f16,       cudaFuncAttributeMaxDynamicSharedMemorySize, GEMM_SMEM);
    cudaFuncSetAttribute(gemm_gates,     cudaFuncAttributeMaxDynamicSharedMemorySize, GG_SMEM);

    float *px, *pS1, *pgx, *pgm;
    __half *phH, *phL, *pZH, *pZL, *pWpH, *pWpL;
    cudaGetSymbolAddress((void**)&px,   g_x);
    cudaGetSymbolAddress((void**)&pS1,  g_S1);
    cudaGetSymbolAddress((void**)&pgx,  g_gx);
    cudaGetSymbolAddress((void**)&pgm,  g_gm);
    cudaGetSymbolAddress((void**)&phH,  g_hH);
    cudaGetSymbolAddress((void**)&phL,  g_hL);
    cudaGetSymbolAddress((void**)&pZH,  g_ZH);
    cudaGetSymbolAddress((void**)&pZL,  g_ZL);
    cudaGetSymbolAddress((void**)&pWpH, g_WpackTH);
    cudaGetSymbolAddress((void**)&pWpL, g_WpackTL);

    pack_kernel<<<192, 256>>>(msg_W, in_W, in_W0, msg_W0, W_hh, W_ih, msg_b);
    input_kernel<<<152, 768, IN_SMEM>>>(q, row, col, d_emb, r_emb, c_emb, in_b);
    sgemm_awt<<<dim3(384/64, NNODE/64), 256>>>(px, W_ih, pgx, 384, 192, 0);

    for (int t = 0; t < TSTEPS; t++) {
        // S1[:, 0:192] = h @ [W0a; W0b]^T  (edge consumes only these cols)
        gemm_f16<<<dim3(3, NNODE/64), 256, GEMM_SMEM>>>(phH, phL, pWpH, pWpL, pS1, 576);
        edge_tc_kernel<<<EGRID, 512, EK_SMEM>>>(msg_b);
        // gm = [h|Z] @ [Whh; Wcomb]^T  (absorbs recurrent term; h zeroed at t=0)
        gemm_gates<<<dim3(6, NNODE/64), 256, GG_SMEM>>>(phH, phL, pZH, pZL, pgm, t);
        lstm_kernel<<<NNODE/8, 768>>>(out_W, out_b, t);
    }

    finalize_kernel<<<(TSTEPS*NNODE + 255)/256, 256>>>(labels, out, out_size);
    loss_kernel<<<1, 1>>>(out, out_size);
}

// round 17
// speedup vs baseline: 1.0389x; 1.0389x over previous
#include <cuda_runtime.h>
#include <cuda_fp16.h>
#include <math.h>
#include <stdint.h>

#define NB     128
#define NCELLS 81
#define NNODE  (NB*NCELLS)     // 10368
#define HD     96
#define TSTEPS 16
#define NTILES (NNODE/6)       // 1728 tiles of 6 nodes (120 edges + 8 pad)
#define CORR   (1.0f/2048.0f)
#define EGRID  152

// ========================= fp16 mma/ldmatrix helpers (sm_80+) =========================
#define MMAF(c,a0,a1,a2,a3,b0,b1) \
    asm volatile("mma.sync.aligned.m16n8k16.row.col.f32.f16.f16.f32 " \
        "{%0,%1,%2,%3}, {%4,%5,%6,%7}, {%8,%9}, {%0,%1,%2,%3};" \
        : "+f"((c)[0]),"+f"((c)[1]),"+f"((c)[2]),"+f"((c)[3]) \
        : "r"(a0),"r"(a1),"r"(a2),"r"(a3), "r"(b0),"r"(b1))
#define LDSM4(r0,r1,r2,r3,addr) \
    asm volatile("ldmatrix.sync.aligned.m8n8.x4.shared.b16 {%0,%1,%2,%3}, [%4];" \
        : "=r"(r0),"=r"(r1),"=r"(r2),"=r"(r3) : "r"(addr))
#define LDSM4T(r0,r1,r2,r3,addr) \
    asm volatile("ldmatrix.sync.aligned.m8n8.x4.trans.shared.b16 {%0,%1,%2,%3}, [%4];" \
        : "=r"(r0),"=r"(r1),"=r"(r2),"=r"(r3) : "r"(addr))

#define BAR_ARRIVE(id)  asm volatile("bar.arrive %0, 512;" :: "r"(id) : "memory")
#define BAR_SYNC512(id) asm volatile("bar.sync %0, 512;"   :: "r"(id) : "memory")

__device__ __forceinline__ uint32_t smem_u32(const void* p) {
    uint32_t a;
    asm("{ .reg .u64 t; cvta.to.shared.u64 t, %1; cvt.u32.u64 %0, t; }" : "=r"(a) : "l"(p));
    return a;
}
__device__ __forceinline__ uint32_t pk2(float a, float b) {
    __half2 h = __floats2half2_rn(a, b);
    return *(uint32_t*)&h;
}

// ========================= device scratch =========================
__device__ float  g_x[NNODE*HD];
__device__ float  g_gx[NNODE*4*HD];
__device__ float  g_S1[NNODE*6*HD];      // [a_src(96) | a_dst(96) | hW(384)]
__device__ float  g_gm[NNODE*4*HD];
__device__ float  g_c[NNODE*HD];
__device__ float  g_WTin[3*HD*HD];
__device__ float  g_WTin0[48*HD];
__device__ float  g_bc[384];
__device__ __half g_hH[NNODE*104], g_hL[NNODE*104];     // h hi/lo images (stride 104)
__device__ __half g_ZH[NNODE*104], g_ZL[NNODE*104];     // Z hi/lo images
__device__ __half g_Wmsg[4*96*104];                     // [W1h|W1l|W2h|W2l] k-major s104
__device__ __half g_WpackTH[96*576], g_WpackTL[96*576];
__device__ __half g_WcombTH[96*384], g_WcombTL[96*384];
__device__ float  g_logits[(size_t)TSTEPS*NNODE*10];
__device__ double g_loss;

// ========================= weight packing =========================
__global__ void pack_kernel(const float* __restrict__ msg_W,
                            const float* __restrict__ in_W,
                            const float* __restrict__ in_W0,
                            const float* __restrict__ msg_W0,
                            const float* __restrict__ W_hh,
                            const float* __restrict__ W_ih,
                            const float* __restrict__ msg_b)
{
    int i = blockIdx.x*blockDim.x + threadIdx.x;
    int stride = gridDim.x*blockDim.x;
    for (int idx = i; idx < 3*HD*HD; idx += stride) {
        int l = idx / (HD*HD), r = idx % (HD*HD);
        int k = r / HD, j = r % HD;
        g_WTin[idx] = in_W[l*HD*HD + j*HD + k];
    }
    for (int idx = i; idx < 48*HD; idx += stride) {
        int k = idx / HD, j = idx % HD;
        g_WTin0[idx] = in_W0[j*48 + k];
    }
    for (int idx = i; idx < 4*96*104; idx += stride) {
        int part = idx / (96*104);
        int r2 = idx % (96*104);
        int k = r2 / 104, j = r2 % 104;
        int layer = part >> 1, which = part & 1;
        float w = (j < 96) ? msg_W[layer*HD*HD + j*HD + k] : 0.f;
        __half hh = __float2half_rn(w);
        g_Wmsg[idx] = which ? __float2half_rn((w - __half2float(hh))*2048.f) : hh;
    }
    for (int idx = i; idx < 96*576; idx += stride) {
        int k = idx / 576, o = idx % 576;
        float v;
        if (o < 96)       v = msg_W0[o*192 + k];
        else if (o < 192) v = msg_W0[(o-96)*192 + 96 + k];
        else              v = W_hh[(o-192)*HD + k];
        __half hh = __float2half_rn(v);
        g_WpackTH[idx] = hh;
        g_WpackTL[idx] = __float2half_rn((v - __half2float(hh))*2048.f);
    }
    for (int idx = i; idx < 96*384; idx += stride) {
        int k = idx / 384, o = idx % 384;
        float s = 0.f;
        const float* wm = W_ih + o*192 + 96;
        const float* w3 = msg_W + 2*HD*HD + k;
        #pragma unroll 8
        for (int c = 0; c < 96; c++) s = fmaf(wm[c], w3[c*96], s);
        __half hh = __float2half_rn(s);
        g_WcombTH[idx] = hh;
        g_WcombTL[idx] = __float2half_rn((s - __half2float(hh))*2048.f);
    }
    for (int idx = i; idx < 384; idx += stride) {
        float s = 0.f;
        #pragma unroll 8
        for (int c = 0; c < 96; c++) s = fmaf(W_ih[idx*192+96+c], msg_b[288+c], s);
        g_bc[idx] = 20.f * s;
    }
    if (i == 0) g_loss = 0.0;
}

// ========================= fp32 sgemm (gx, once) =========================
__global__ void __launch_bounds__(256) sgemm_awt(const float* __restrict__ A,
                                                 const float* __restrict__ W,
                                                 float* __restrict__ C,
                                                 int Nc, int ldw, int woff)
{
    __shared__ float As[16][68];
    __shared__ float Ws[16][68];
    int bm = blockIdx.y * 64, bn = blockIdx.x * 64;
    int tid = threadIdx.x;
    int tx = tid & 15, ty = tid >> 4;
    int lr = tid >> 2, lk = (tid & 3) << 2;
    float acc[4][4];
    #pragma unroll
    for (int i = 0; i < 4; i++)
        #pragma unroll
        for (int j = 0; j < 4; j++) acc[i][j] = 0.f;

    for (int k0 = 0; k0 < 96; k0 += 16) {
        float4 a = *(const float4*)(A + (size_t)(bm+lr)*96 + k0 + lk);
        As[lk+0][lr]=a.x; As[lk+1][lr]=a.y; As[lk+2][lr]=a.z; As[lk+3][lr]=a.w;
        float4 w = *(const float4*)(W + (size_t)(bn+lr)*ldw + woff + k0 + lk);
        Ws[lk+0][lr]=w.x; Ws[lk+1][lr]=w.y; Ws[lk+2][lr]=w.z; Ws[lk+3][lr]=w.w;
        __syncthreads();
        #pragma unroll
        for (int k = 0; k < 16; k++) {
            float4 a4 = *(const float4*)&As[k][ty*4];
            float4 w4 = *(const float4*)&Ws[k][tx*4];
            float av[4] = {a4.x, a4.y, a4.z, a4.w};
            float wv[4] = {w4.x, w4.y, w4.z, w4.w};
            #pragma unroll
            for (int i = 0; i < 4; i++)
                #pragma unroll
                for (int j = 0; j < 4; j++)
                    acc[i][j] = fmaf(av[i], wv[j], acc[i][j]);
        }
        __syncthreads();
    }
    #pragma unroll
    for (int i = 0; i < 4; i++) {
        float4 o = make_float4(acc[i][0], acc[i][1], acc[i][2], acc[i][3]);
        *(float4*)(C + (size_t)(bm + ty*4 + i)*Nc + bn + tx*4) = o;
    }
}

// ========================= fp16 3-term GEMM: C = A @ W^T =========================
#define GEMM_SMEM (2*64*104*2 + 2*96*72*2)   // 54272

__global__ void __launch_bounds__(256) gemm_f16(const __half* __restrict__ AH,
                                                const __half* __restrict__ AL,
                                                const __half* __restrict__ BH,
                                                const __half* __restrict__ BL,
                                                float* __restrict__ C, int Nc)
{
    extern __shared__ char sg[];
    __half* sA = (__half*)sg;
    __half* sB = (__half*)(sg + 2*64*104*2);
    int bm = blockIdx.y*64, bn = blockIdx.x*64;
    int tid = threadIdx.x, lane = tid & 31, wid = tid >> 5;

    {
        const uint4* gh = (const uint4*)(AH + (size_t)bm*104);
        const uint4* gl = (const uint4*)(AL + (size_t)bm*104);
        uint4* dh = (uint4*)sA;
        uint4* dl = (uint4*)(sA + 64*104);
        for (int i = tid; i < 832; i += 256) { dh[i] = gh[i]; dl[i] = gl[i]; }
        for (int i = tid; i < 2*96*8; i += 256) {
            int part = i / 768, r2 = i % 768;
            int k = r2 >> 3, c8 = (r2 & 7) * 8;
            const __half* src = (part ? BL : BH) + (size_t)k*Nc + bn + c8;
            *(uint4*)(sB + part*96*72 + k*72 + c8) = *(const uint4*)src;
        }
    }
    __syncthreads();

    int mtile = wid >> 1, nhalf = wid & 1;
    uint32_t aHb = smem_u32(sA) + (uint32_t)(((mtile*16 + (lane&15))*104 + ((lane>>4)<<3))*2);
    uint32_t aLb = aHb + 64*104*2;
    uint32_t bHb = smem_u32(sB) + (uint32_t)((((lane&15))*72 + nhalf*32 + ((lane>>4)<<3))*2);
    uint32_t bLb = bHb + 96*72*2;

    float am[4][4], ac[4][4];
    #pragma unroll
    for (int nt = 0; nt < 4; nt++)
        #pragma unroll
        for (int j = 0; j < 4; j++) { am[nt][j] = 0.f; ac[nt][j] = 0.f; }

    #pragma unroll
    for (int kt = 0; kt < 6; kt++) {
        uint32_t A0,A1,A2,A3, L0,L1,L2,L3;
        LDSM4(A0,A1,A2,A3, aHb + kt*32);
        LDSM4(L0,L1,L2,L3, aLb + kt*32);
        uint32_t h0,h1,h2,h3, hh0,hh1,hh2,hh3;
        uint32_t l0,l1,l2,l3, ll0,ll1,ll2,ll3;
        LDSM4T(h0,h1,h2,h3,     bHb + kt*2304);
        LDSM4T(hh0,hh1,hh2,hh3, bHb + kt*2304 + 32);
        LDSM4T(l0,l1,l2,l3,     bLb + kt*2304);
        LDSM4T(ll0,ll1,ll2,ll3, bLb + kt*2304 + 32);
        MMAF(am[0], A0,A1,A2,A3, h0,h1);
        MMAF(am[1], A0,A1,A2,A3, h2,h3);
        MMAF(am[2], A0,A1,A2,A3, hh0,hh1);
        MMAF(am[3], A0,A1,A2,A3, hh2,hh3);
        MMAF(ac[0], L0,L1,L2,L3, h0,h1);
        MMAF(ac[1], L0,L1,L2,L3, h2,h3);
        MMAF(ac[2], L0,L1,L2,L3, hh0,hh1);
        MMAF(ac[3], L0,L1,L2,L3, hh2,hh3);
        MMAF(ac[0], A0,A1,A2,A3, l0,l1);
        MMAF(ac[1], A0,A1,A2,A3, l2,l3);
        MMAF(ac[2], A0,A1,A2,A3, ll0,ll1);
        MMAF(ac[3], A0,A1,A2,A3, ll2,ll3);
    }

    int r0 = mtile*16 + (lane >> 2);
    int cb = (lane & 3) * 2;
    #pragma unroll
    for (int nt = 0; nt < 4; nt++) {
        int c = bn + nhalf*32 + nt*8 + cb;
        *(float2*)(C + (size_t)(bm+r0)*Nc + c) =
            make_float2(am[nt][0] + ac[nt][0]*CORR, am[nt][1] + ac[nt][1]*CORR);
        *(float2*)(C + (size_t)(bm+r0+8)*Nc + c) =
            make_float2(am[nt][2] + ac[nt][2]*CORR, am[nt][3] + ac[nt][3]*CORR);
    }
}

// ========================= input embedding + MLP =========================
__device__ __forceinline__ float dot96(const float* __restrict__ WTcol,
                                       const float* __restrict__ vin)
{
    float s = 0.f;
    #pragma unroll 8
    for (int k4 = 0; k4 < 24; k4++) {
        float4 a = ((const float4*)vin)[k4];
        s = fmaf(WTcol[(4*k4+0)*96], a.x, s);
        s = fmaf(WTcol[(4*k4+1)*96], a.y, s);
        s = fmaf(WTcol[(4*k4+2)*96], a.z, s);
        s = fmaf(WTcol[(4*k4+3)*96], a.w, s);
    }
    return s;
}

__global__ void __launch_bounds__(768) input_kernel(const int* __restrict__ q,
    const int* __restrict__ rw, const int* __restrict__ cl,
    const float* __restrict__ demb, const float* __restrict__ remb,
    const float* __restrict__ cemb, const float* __restrict__ inb)
{
    extern __shared__ float sm[];
    float* sW0 = sm;
    float* sWT = sm + 48*96;
    float* svb = sWT + 3*9216;
    for (int i = threadIdx.x; i < 48*96;  i += 768) sW0[i] = g_WTin0[i];
    for (int i = threadIdx.x; i < 3*9216; i += 768) sWT[i] = g_WTin[i];
    __syncthreads();

    int slot = threadIdx.x / 96, j = threadIdx.x % 96;
    float* v0 = svb + slot*240;
    float* vA = v0 + 48;
    float* vB = vA + 96;
    int sg = blockIdx.x*8 + slot;
    int stride = gridDim.x*8;
    int iters = (NNODE + stride - 1) / stride;
    float b0 = inb[j], b1 = inb[96+j], b2 = inb[192+j], b3 = inb[288+j];

    for (int it = 0; it < iters; it++) {
        int node = sg + it*stride;
        bool act = node < NNODE;
        int n = act ? node : NNODE-1;
        if (j < 16)      v0[j] = demb[q[n]*16 + j];
        else if (j < 32) v0[j] = remb[rw[n]*16 + (j-16)];
        else if (j < 48) v0[j] = cemb[cl[n]*16 + (j-32)];
        __syncthreads();
        float s = b0;
        #pragma unroll
        for (int k4 = 0; k4 < 12; k4++) {
            float4 a = ((const float4*)v0)[k4];
            s = fmaf(sW0[(4*k4+0)*96+j], a.x, s);
            s = fmaf(sW0[(4*k4+1)*96+j], a.y, s);
            s = fmaf(sW0[(4*k4+2)*96+j], a.z, s);
            s = fmaf(sW0[(4*k4+3)*96+j], a.w, s);
        }
        vA[j] = fmaxf(s, 0.f);
        __syncthreads();
        float t1 = b1 + dot96(sWT + j, vA);
        vB[j] = fmaxf(t1, 0.f);
        __syncthreads();
        float t2 = b2 + dot96(sWT + 9216 + j, vB);
        vA[j] = fmaxf(t2, 0.f);
        __syncthreads();
        float t3 = b3 + dot96(sWT + 2*9216 + j, vA);
        if (act) {
            g_x[(size_t)node*96 + j] = t3;
            __half hh = __float2half_rn(t3);
            g_hH[(size_t)node*104 + j] = hh;
            g_hL[(size_t)node*104 + j] = __float2half_rn((t3 - __half2float(hh))*2048.f);
            g_c[(size_t)node*96 + j] = 0.f;
        }
        __syncthreads();
    }
}

// ========================= warp-specialized fp16 HMMA edge pipeline =========================
#define OFF_B0     0
#define OFF_B1     384
#define OFF_B2     768
#define OFF_NBR    1152
#define OFF_W      7680
#define OFF_A      87552
#define ARS        432
#define SLOT       (128*ARS)
#define EK_SMEM    (OFF_A + 2*SLOT)  // 198144
#define WIMG       19968

__device__ __forceinline__ void edge_layer12(uint32_t aH, uint32_t aL,
                                             uint32_t wH, uint32_t wL,
                                             float (*am)[4], float (*ac)[4])
{
    #pragma unroll
    for (int kt = 0; kt < 6; kt++) {
        uint32_t A0,A1,A2,A3, L0,L1,L2,L3;
        LDSM4(A0,A1,A2,A3, aH + kt*32);
        LDSM4(L0,L1,L2,L3, aL + kt*32);
        #pragma unroll
        for (int np = 0; np < 3; np++) {
            uint32_t h0,h1,h2,h3, hh0,hh1,hh2,hh3;
            uint32_t l0,l1,l2,l3, ll0,ll1,ll2,ll3;
            uint32_t base = kt*3328 + np*64;
            LDSM4T(h0,h1,h2,h3,     wH + base);
            LDSM4T(hh0,hh1,hh2,hh3, wH + base + 32);
            LDSM4T(l0,l1,l2,l3,     wL + base);
            LDSM4T(ll0,ll1,ll2,ll3, wL + base + 32);
            int n0 = np*4;
            MMAF(am[n0  ], A0,A1,A2,A3, h0,h1);
            MMAF(am[n0+1], A0,A1,A2,A3, h2,h3);
            MMAF(am[n0+2], A0,A1,A2,A3, hh0,hh1);
            MMAF(am[n0+3], A0,A1,A2,A3, hh2,hh3);
            MMAF(ac[n0  ], L0,L1,L2,L3, h0,h1);
            MMAF(ac[n0+1], L0,L1,L2,L3, h2,h3);
            MMAF(ac[n0+2], L0,L1,L2,L3, hh0,hh1);
            MMAF(ac[n0+3], L0,L1,L2,L3, hh2,hh3);
            MMAF(ac[n0  ], A0,A1,A2,A3, l0,l1);
            MMAF(ac[n0+1], A0,A1,A2,A3, l2,l3);
            MMAF(ac[n0+2], A0,A1,A2,A3, ll0,ll1);
            MMAF(ac[n0+3], A0,A1,A2,A3, ll2,ll3);
        }
    }
}

__device__ __forceinline__ void build_tile(char* slotc, int g, int rB, int half,
                                           const int* __restrict__ snbr,
                                           const float* __restrict__ sb0)
{
    char* rowb = slotc + rB*ARS;
    if (rB < 120) {
        int dnode = g*6 + rB/20;
        int cell = dnode % 81;
        int srcn = dnode - cell + snbr[cell*20 + (rB % 20)];
        const float4* aS = (const float4*)(g_S1 + (size_t)srcn*576 + half*48);
        const float4* aD = (const float4*)(g_S1 + (size_t)dnode*576 + 96 + half*48);
        const float4* bB = (const float4*)(sb0 + half*48);
        #pragma unroll 4
        for (int k4 = 0; k4 < 12; k4++) {
            float4 s = aS[k4], d = aD[k4], b = bB[k4];
            float v0 = fmaxf(s.x+d.x+b.x, 0.f);
            float v1 = fmaxf(s.y+d.y+b.y, 0.f);
            float v2 = fmaxf(s.z+d.z+b.z, 0.f);
            float v3 = fmaxf(s.w+d.w+b.w, 0.f);
            int c = half*48 + k4*4;
            uint32_t h01 = pk2(v0, v1), h23 = pk2(v2, v3);
            float2 f01 = __half22float2(*(__half2*)&h01);
            float2 f23 = __half22float2(*(__half2*)&h23);
            *(uint32_t*)(rowb + c*2)           = h01;
            *(uint32_t*)(rowb + c*2 + 4)       = h23;
            *(uint32_t*)(rowb + 208 + c*2)     = pk2((v0-f01.x)*2048.f, (v1-f01.y)*2048.f);
            *(uint32_t*)(rowb + 208 + c*2 + 4) = pk2((v2-f23.x)*2048.f, (v3-f23.y)*2048.f);
        }
    } else {
        #pragma unroll 4
        for (int k4 = 0; k4 < 12; k4++) {
            int c = half*48 + k4*4;
            *(uint32_t*)(rowb + c*2)           = 0u;
            *(uint32_t*)(rowb + c*2 + 4)       = 0u;
            *(uint32_t*)(rowb + 208 + c*2)     = 0u;
            *(uint32_t*)(rowb + 208 + c*2 + 4) = 0u;
        }
    }
}

__global__ void __launch_bounds__(512, 1) edge_tc_kernel(const float* __restrict__ msgb)
{
    extern __shared__ char smc[];
    uint32_t sbase = smem_u32(smc);
    float* sb0 = (float*)(smc + OFF_B0);
    float* sb1 = (float*)(smc + OFF_B1);
    float* sb2 = (float*)(smc + OFF_B2);
    int*  snbr = (int*)(smc + OFF_NBR);
    int tid = threadIdx.x, lane = tid & 31, wid = tid >> 5;

    if (tid < 96) { sb0[tid]=msgb[tid]; sb1[tid]=msgb[96+tid]; sb2[tid]=msgb[192+tid]; }
    if (tid < 81) {
        int u = tid;
        int ru = u/9, cu = u%9, bu = (ru/3)*3 + cu/3;
        int cnt = 0;
        for (int v = 0; v < 81; v++) {
            if (v == u) continue;
            int rv = v/9, cv = v%9, bv = (rv/3)*3 + cv/3;
            if (rv == ru || cv == cu || bv == bu) snbr[u*20 + cnt++] = v;
        }
    }
    for (int i = tid; i < 4992; i += 512)
        ((uint4*)(smc + OFF_W))[i] = ((const uint4*)g_Wmsg)[i];
    __syncthreads();

    int bid = blockIdx.x;
    int n = (NTILES - bid + EGRID - 1) / EGRID;

    if (wid < 8) {
        int w = wid;
        uint32_t wfo = (uint32_t)((((lane&15))*104 + ((lane>>4)<<3))*2);
        uint32_t w1h = sbase + OFF_W + wfo;
        uint32_t w1l = w1h + WIMG;
        uint32_t w2h = w1h + 2*WIMG;
        uint32_t w2l = w1h + 3*WIMG;
        int cb = (lane & 3) * 2;
        int rfr = lane >> 2;
        int s = 0;

        for (int it = 0; it < n; it++) {
            BAR_SYNC512(1+s);
            char* slotc = smc + OFF_A + s*SLOT;
            uint32_t slotu = sbase + OFF_A + s*SLOT;
            uint32_t aH = slotu + (uint32_t)((w*16 + (lane&15))*ARS + ((lane>>4)<<4));
            uint32_t aL = aH + 208;

            float am[12][4], ac[12][4];
            #pragma unroll
            for (int nt = 0; nt < 12; nt++) {
                int c = nt*8 + cb;
                am[nt][0]=sb1[c]; am[nt][1]=sb1[c+1]; am[nt][2]=sb1[c]; am[nt][3]=sb1[c+1];
                ac[nt][0]=0.f; ac[nt][1]=0.f; ac[nt][2]=0.f; ac[nt][3]=0.f;
            }
            edge_layer12(aH, aL, w1h, w1l, am, ac);
            {
                int r0 = w*16 + rfr;
                char* rA0 = slotc + r0*ARS;
                char* rA8 = slotc + (r0+8)*ARS;
                #pragma unroll
                for (int nt = 0; nt < 12; nt++) {
                    int c = nt*8 + cb;
                    float v0 = fmaxf(am[nt][0] + ac[nt][0]*CORR, 0.f);
                    float v1 = fmaxf(am[nt][1] + ac[nt][1]*CORR, 0.f);
                    float v2 = fmaxf(am[nt][2] + ac[nt][2]*CORR, 0.f);
                    float v3 = fmaxf(am[nt][3] + ac[nt][3]*CORR, 0.f);
                    uint32_t h01 = pk2(v0, v1), h23 = pk2(v2, v3);
                    float2 f01 = __half22float2(*(__half2*)&h01);
                    float2 f23 = __half22float2(*(__half2*)&h23);
                    *(uint32_t*)(rA0 + c*2)       = h01;
                    *(uint32_t*)(rA8 + c*2)       = h23;
                    *(uint32_t*)(rA0 + 208 + c*2) = pk2((v0-f01.x)*2048.f, (v1-f01.y)*2048.f);
                    *(uint32_t*)(rA8 + 208 + c*2) = pk2((v2-f23.x)*2048.f, (v3-f23.y)*2048.f);
                }
            }
            __syncwarp();

            #pragma unroll
            for (int nt = 0; nt < 12; nt++) {
                int c = nt*8 + cb;
                am[nt][0]=sb2[c]; am[nt][1]=sb2[c+1]; am[nt][2]=sb2[c]; am[nt][3]=sb2[c+1];
                ac[nt][0]=0.f; ac[nt][1]=0.f; ac[nt][2]=0.f; ac[nt][3]=0.f;
            }
            edge_layer12(aH, aL, w2h, w2l, am, ac);
            {
                float* stg = (float*)slotc;
                int r0 = w*16 + rfr;
                #pragma unroll
                for (int nt = 0; nt < 12; nt++) {
                    int c = nt*8 + cb;
                    stg[r0*108 + c]       = fmaxf(am[nt][0] + ac[nt][0]*CORR, 0.f);
                    stg[r0*108 + c + 1]   = fmaxf(am[nt][1] + ac[nt][1]*CORR, 0.f);
                    stg[(r0+8)*108 + c]   = fmaxf(am[nt][2] + ac[nt][2]*CORR, 0.f);
                    stg[(r0+8)*108 + c+1] = fmaxf(am[nt][3] + ac[nt][3]*CORR, 0.f);
                }
            }
            BAR_ARRIVE(3+s);
            s ^= 1;
        }
    } else {
        int t = tid - 256;
        int rB = t & 127, half = t >> 7;

        build_tile(smc + OFF_A,        bid,         rB, half, snbr, sb0);
        BAR_ARRIVE(1);
        build_tile(smc + OFF_A + SLOT, bid + EGRID, rB, half, snbr, sb0);
        BAR_ARRIVE(2);

        int s = 0;
        for (int it = 0; it < n; it++) {
            BAR_SYNC512(3+s);
            float* stg = (float*)(smc + OFF_A + s*SLOT);
            int g = bid + it*EGRID;
            for (int idx = t; idx < 576; idx += 256) {
                int i = idx / 96, c = idx % 96;
                float sum = 0.f;
                #pragma unroll
                for (int e = 0; e < 20; e++) sum += stg[(i*20+e)*108 + c];
                __half hh = __float2half_rn(sum);
                size_t o = (size_t)(g*6+i)*104 + c;
                g_ZH[o] = hh;
                g_ZL[o] = __float2half_rn((sum - __half2float(hh))*2048.f);
            }
            int itn = it + 2;
            if (itn < n)
                build_tile(smc + OFF_A + s*SLOT, bid + itn*EGRID, rB, half, snbr, sb0);
            BAR_ARRIVE(1+s);
            s ^= 1;
        }
    }
}

// ========================= LSTM pointwise + per-step logits =========================
__global__ void __launch_bounds__(768) lstm_kernel(const float* __restrict__ outW,
                                                   const float* __restrict__ outb, int t)
{
    int slot = threadIdx.x / 96, j = threadIdx.x % 96;
    int n = blockIdx.x*8 + slot;
    __shared__ float sh[8][HD];
    size_t b4 = (size_t)n*384 + j;
    float gi = g_gx[b4      ] + g_gm[b4      ] + g_bc[j];
    float gf = g_gx[b4 +  96] + g_gm[b4 +  96] + g_bc[96+j];
    float gg = g_gx[b4 + 192] + g_gm[b4 + 192] + g_bc[192+j];
    float go = g_gx[b4 + 288] + g_gm[b4 + 288] + g_bc[288+j];
    if (t > 0) {
        const float* hw = g_S1 + (size_t)n*576 + 192 + j;
        gi += hw[0]; gf += hw[96]; gg += hw[192]; go += hw[288];
    }
    float si = 1.f/(1.f + expf(-gi));
    float sf = 1.f/(1.f + expf(-gf));
    float so = 1.f/(1.f + expf(-go));
    float cn = sf * g_c[(size_t)n*96 + j] + si * tanhf(gg);
    float hn = so * tanhf(cn);
    g_c[(size_t)n*96 + j] = cn;
    __half hh = __float2half_rn(hn);
    g_hH[(size_t)n*104 + j] = hh;
    g_hL[(size_t)n*104 + j] = __float2half_rn((hn - __half2float(hh))*2048.f);
    sh[slot][j] = hn;
    __syncthreads();
    if (j < 10) {
        float s = outb[j];
        const float* w = outW + j*96;
        #pragma unroll 8
        for (int k = 0; k < 96; k++) s = fmaf(sh[slot][k], w[k], s);
        g_logits[((size_t)t*NNODE + n)*10 + j] = s;
    }
}

// ========================= preds / loss / lf =========================
__global__ void finalize_kernel(const int* __restrict__ labels,
                                float* __restrict__ out, int out_size)
{
    int idx = blockIdx.x*blockDim.x + threadIdx.x;
    double term = 0.0;
    if (idx < TSTEPS*NNODE) {
        const float* l = g_logits + (size_t)idx*10;
        float mx = l[0]; int am = 0;
        #pragma unroll
        for (int d = 1; d < 10; d++) if (l[d] > mx) { mx = l[d]; am = d; }
        float se = 0.f;
        #pragma unroll
        for (int d = 0; d < 10; d++) se += expf(l[d] - mx);
        float lse = mx + logf(se);
        int lab = labels[idx % NNODE];
        term = (double)(lse - l[lab]);

        const int FULL = TSTEPS*NNODE*11 + 1;
        if (out_size >= FULL) {
            out[idx] = (float)am;
            float* lf = out + TSTEPS*NNODE + 1 + (size_t)idx*10;
            #pragma unroll
            for (int d = 0; d < 10; d++) lf[d] = l[d];
        } else {
            float* lf = out + (size_t)idx*10;
            #pragma unroll
            for (int d = 0; d < 10; d++) lf[d] = l[d];
        }
    }
    #pragma unroll
    for (int o = 16; o; o >>= 1)
        term += __shfl_down_sync(0xffffffffu, term, o);
    if ((threadIdx.x & 31) == 0 && term != 0.0) atomicAdd(&g_loss, term);
}

__global__ void loss_kernel(float* __restrict__ out, int out_size)
{
    const int FULL = TSTEPS*NNODE*11 + 1;
    if (out_size >= FULL)
        out[TSTEPS*NNODE] = (float)(g_loss / (double)(TSTEPS*NNODE));
}

// ========================= launch =========================
extern "C" void kernel_launch(void* const* d_in, const int* in_sizes, int n_in,
                              void* d_out, int out_size)
{
    const int*   q      = (const int*)  d_in[0];
    const int*   row    = (const int*)  d_in[1];
    const int*   col    = (const int*)  d_in[2];
    const int*   labels = (const int*)  d_in[3];
    const float* d_emb  = (const float*)d_in[6];
    const float* r_emb  = (const float*)d_in[7];
    const float* c_emb  = (const float*)d_in[8];
    const float* in_W0  = (const float*)d_in[9];
    const float* in_W   = (const float*)d_in[10];
    const float* in_b   = (const float*)d_in[11];
    const float* msg_W0 = (const float*)d_in[12];
    const float* msg_W  = (const float*)d_in[13];
    const float* msg_b  = (const float*)d_in[14];
    const float* W_ih   = (const float*)d_in[15];
    const float* W_hh   = (const float*)d_in[16];
    const float* out_W  = (const float*)d_in[17];
    const float* out_b  = (const float*)d_in[18];
    float* out = (float*)d_out;

    const int IN_SMEM = (48*96 + 3*9216 + 8*240) * 4;
    cudaFuncSetAttribute(input_kernel,   cudaFuncAttributeMaxDynamicSharedMemorySize, IN_SMEM);
    cudaFuncSetAttribute(edge_tc_kernel, cudaFuncAttributeMaxDynamicSharedMemorySize, EK_SMEM);
    cudaFuncSetAttribute(gemm_f16,       cudaFuncAttributeMaxDynamicSharedMemorySize, GEMM_SMEM);

    float *px, *pS1, *pgx, *pgm;
    __half *phH, *phL, *pZH, *pZL, *pWpH, *pWpL, *pWcH, *pWcL;
    cudaGetSymbolAddress((void**)&px,   g_x);
    cudaGetSymbolAddress((void**)&pS1,  g_S1);
    cudaGetSymbolAddress((void**)&pgx,  g_gx);
    cudaGetSymbolAddress((void**)&pgm,  g_gm);
    cudaGetSymbolAddress((void**)&phH,  g_hH);
    cudaGetSymbolAddress((void**)&phL,  g_hL);
    cudaGetSymbolAddress((void**)&pZH,  g_ZH);
    cudaGetSymbolAddress((void**)&pZL,  g_ZL);
    cudaGetSymbolAddress((void**)&pWpH, g_WpackTH);
    cudaGetSymbolAddress((void**)&pWpL, g_WpackTL);
    cudaGetSymbolAddress((void**)&pWcH, g_WcombTH);
    cudaGetSymbolAddress((void**)&pWcL, g_WcombTL);

    pack_kernel<<<192, 256>>>(msg_W, in_W, in_W0, msg_W0, W_hh, W_ih, msg_b);
    input_kernel<<<152, 768, IN_SMEM>>>(q, row, col, d_emb, r_emb, c_emb, in_b);
    sgemm_awt<<<dim3(384/64, NNODE/64), 256>>>(px, W_ih, pgx, 384, 192, 0);

    for (int t = 0; t < TSTEPS; t++) {
        gemm_f16<<<dim3(9, NNODE/64), 256, GEMM_SMEM>>>(phH, phL, pWpH, pWpL, pS1, 576);
        edge_tc_kernel<<<EGRID, 512, EK_SMEM>>>(msg_b);
        gemm_f16<<<dim3(6, NNODE/64), 256, GEMM_SMEM>>>(pZH, pZL, pWcH, pWcL, pgm, 384);
        lstm_kernel<<<NNODE/8, 768>>>(out_W, out_b, t);
    }

    finalize_kernel<<<(TSTEPS*NNODE + 255)/256, 256>>>(labels, out, out_size);
    loss_kernel<<<1, 1>>>(out, out_size);
}